// round 7
// baseline (speedup 1.0000x reference)
#include <cuda_runtime.h>
#include <cuda_bf16.h>
#include <cstdint>
#include <math.h>

#define BB 2
#define SS 2048
#define HH 1024
#define NHEADS 16
#define HDIM 64
#define MTOT (BB*SS)      // 4096
#define NQKV (3*HH)       // 3072

// Scratch (allocation-free rule: __device__ globals)
__device__ __nv_bfloat16 g_qkv_bf[(size_t)MTOT * NQKV];  // 24 MiB (Q pre-scaled 1/8)
__device__ __nv_bfloat16 g_ctx_bf[(size_t)MTOT * HH];    // 8 MiB
__device__ float g_x[(size_t)MTOT * HH];                 // 16 MiB
__device__ int8_t g_A8[(size_t)MTOT * HH];               // 4 MiB (hidden, int8)
__device__ int8_t g_C8[(size_t)MTOT * HH];               // 4 MiB (ctx, int8)
__device__ int8_t g_Bq8[(size_t)NQKV * HH];              // 3 MiB (w_qkv^T, int8)
__device__ int8_t g_Bd8[(size_t)HH * HH];                // 1 MiB (w_dense^T, int8)
__device__ float g_saA[MTOT];
__device__ float g_saC[MTOT];
__device__ float g_sbq[NQKV];
__device__ float g_sbd[HH];
__device__ float g_partq[16 * NQKV];
__device__ float g_partd[16 * HH];

// ============================================================================
// helpers
// ============================================================================
__device__ __forceinline__ uint32_t smem_u32(const void* p) {
    uint32_t a;
    asm("{ .reg .u64 t; cvta.to.shared.u64 t, %1; cvt.u32.u64 %0, t; }"
        : "=r"(a) : "l"(p));
    return a;
}
__device__ __forceinline__ void cpasync16(uint32_t s, const void* g) {
    asm volatile("cp.async.cg.shared.global [%0], [%1], 16;" :: "r"(s), "l"(g));
}
#define CP_COMMIT() asm volatile("cp.async.commit_group;" ::: "memory")
#define CP_WAIT0()  asm volatile("cp.async.wait_group 0;" ::: "memory")
#define CP_WAIT1()  asm volatile("cp.async.wait_group 1;" ::: "memory")
#define CP_WAIT2()  asm volatile("cp.async.wait_group 2;" ::: "memory")

__device__ __forceinline__ uint32_t pack_bf16(float lo, float hi) {
    uint32_t r;
    asm("cvt.rn.bf16x2.f32 %0, %1, %2;" : "=r"(r) : "f"(hi), "f"(lo));
    return r;
}
// bf16 m16n8k16 (attention)
__device__ __forceinline__ void mma_bf16(float c[4], const uint32_t a[4],
                                         const uint32_t b[2]) {
    asm volatile(
        "mma.sync.aligned.m16n8k16.row.col.f32.bf16.bf16.f32 "
        "{%0,%1,%2,%3}, {%4,%5,%6,%7}, {%8,%9}, {%0,%1,%2,%3};\n"
        : "+f"(c[0]), "+f"(c[1]), "+f"(c[2]), "+f"(c[3])
        : "r"(a[0]), "r"(a[1]), "r"(a[2]), "r"(a[3]), "r"(b[0]), "r"(b[1]));
}
// int8 m16n8k32 (projection GEMMs) — 2x rate vs bf16 expected
__device__ __forceinline__ void mma_s8(int c[4], const uint32_t a[4],
                                       const uint32_t b[2]) {
    asm volatile(
        "mma.sync.aligned.m16n8k32.row.col.s32.s8.s8.s32 "
        "{%0,%1,%2,%3}, {%4,%5,%6,%7}, {%8,%9}, {%0,%1,%2,%3};\n"
        : "+r"(c[0]), "+r"(c[1]), "+r"(c[2]), "+r"(c[3])
        : "r"(a[0]), "r"(a[1]), "r"(a[2]), "r"(a[3]), "r"(b[0]), "r"(b[1]));
}
__device__ __forceinline__ void ldmatrix_x4(uint32_t r[4], uint32_t addr) {
    asm volatile("ldmatrix.sync.aligned.m8n8.x4.shared.b16 {%0,%1,%2,%3}, [%4];"
                 : "=r"(r[0]), "=r"(r[1]), "=r"(r[2]), "=r"(r[3]) : "r"(addr));
}
__device__ __forceinline__ void ldmatrix_x4t(uint32_t r[4], uint32_t addr) {
    asm volatile("ldmatrix.sync.aligned.m8n8.x4.trans.shared.b16 {%0,%1,%2,%3}, [%4];"
                 : "=r"(r[0]), "=r"(r[1]), "=r"(r[2]), "=r"(r[3]) : "r"(addr));
}
__device__ __forceinline__ int8_t q8(float x, float inv_s) {
    int q = __float2int_rn(x * inv_s);
    q = q > 127 ? 127 : (q < -127 ? -127 : q);
    return (int8_t)q;
}

// ============================================================================
// quantization prep
// ============================================================================
// per-row absmax quant of fp32 matrix [rows][1024] -> int8 + scale
__global__ __launch_bounds__(256)
void quantA_f32_kernel(const float* __restrict__ in, int8_t* __restrict__ out,
                       float* __restrict__ sa) {
    const int row = blockIdx.x, tid = threadIdx.x;
    __shared__ float wred[8];
    const float4 v = ((const float4*)(in + (size_t)row * HH))[tid];
    float m = fmaxf(fmaxf(fabsf(v.x), fabsf(v.y)), fmaxf(fabsf(v.z), fabsf(v.w)));
#pragma unroll
    for (int o = 16; o > 0; o >>= 1) m = fmaxf(m, __shfl_xor_sync(~0u, m, o));
    if ((tid & 31) == 0) wred[tid >> 5] = m;
    __syncthreads();
    m = fmaxf(fmaxf(fmaxf(wred[0], wred[1]), fmaxf(wred[2], wred[3])),
              fmaxf(fmaxf(wred[4], wred[5]), fmaxf(wred[6], wred[7])));
    const float s = fmaxf(m, 1e-12f) / 127.0f;
    const float is = 1.0f / s;
    if (tid == 0) sa[row] = s;
    char4 o;
    o.x = q8(v.x, is); o.y = q8(v.y, is); o.z = q8(v.z, is); o.w = q8(v.w, is);
    ((char4*)(out + (size_t)row * HH))[tid] = o;
}
// same, bf16 input (ctx)
__global__ __launch_bounds__(256)
void quantA_bf16_kernel(const __nv_bfloat16* __restrict__ in, int8_t* __restrict__ out,
                        float* __restrict__ sa) {
    const int row = blockIdx.x, tid = threadIdx.x;
    __shared__ float wred[8];
    const uint2 u = ((const uint2*)(in + (size_t)row * HH))[tid];
    const __nv_bfloat162 p0 = *(const __nv_bfloat162*)&u.x;
    const __nv_bfloat162 p1 = *(const __nv_bfloat162*)&u.y;
    float a = __bfloat162float(p0.x), b = __bfloat162float(p0.y);
    float c = __bfloat162float(p1.x), d = __bfloat162float(p1.y);
    float m = fmaxf(fmaxf(fabsf(a), fabsf(b)), fmaxf(fabsf(c), fabsf(d)));
#pragma unroll
    for (int o = 16; o > 0; o >>= 1) m = fmaxf(m, __shfl_xor_sync(~0u, m, o));
    if ((tid & 31) == 0) wred[tid >> 5] = m;
    __syncthreads();
    m = fmaxf(fmaxf(fmaxf(wred[0], wred[1]), fmaxf(wred[2], wred[3])),
              fmaxf(fmaxf(wred[4], wred[5]), fmaxf(wred[6], wred[7])));
    const float s = fmaxf(m, 1e-12f) / 127.0f;
    const float is = 1.0f / s;
    if (tid == 0) sa[row] = s;
    char4 o;
    o.x = q8(a, is); o.y = q8(b, is); o.z = q8(c, is); o.w = q8(d, is);
    ((char4*)(out + (size_t)row * HH))[tid] = o;
}
// column absmax partials: part[by][col] = max |w[by*64 .. +64][col]|
__global__ __launch_bounds__(256)
void colmax_part_kernel(const float* __restrict__ w, float* __restrict__ part, int N) {
    const int col = blockIdx.x * 256 + threadIdx.x;
    const int r0 = blockIdx.y * 64;
    float m = 0.0f;
#pragma unroll 8
    for (int r = 0; r < 64; r++)
        m = fmaxf(m, fabsf(w[(size_t)(r0 + r) * N + col]));
    part[(size_t)blockIdx.y * N + col] = m;
}
__global__ __launch_bounds__(256)
void colmax_fin_kernel(const float* __restrict__ part, float* __restrict__ sb, int N) {
    const int col = blockIdx.x * 256 + threadIdx.x;
    float m = 0.0f;
#pragma unroll
    for (int i = 0; i < 16; i++) m = fmaxf(m, part[(size_t)i * N + col]);
    sb[col] = fmaxf(m, 1e-12f) / 127.0f;
}
// transpose + quantize: w[K][N] fp32 -> out[N][K] int8 (scale per n)
__global__ void quantB_T_kernel(const float* __restrict__ w, const float* __restrict__ sb,
                                int8_t* __restrict__ out, int Kdim, int N) {
    __shared__ float t[32][33];
    const int n0 = blockIdx.x * 32, k0 = blockIdx.y * 32;
    const int tx = threadIdx.x, ty = threadIdx.y;  // 32 x 8
#pragma unroll
    for (int i = 0; i < 4; i++)
        t[ty + i * 8][tx] = w[(size_t)(k0 + ty + i * 8) * N + n0 + tx];
    __syncthreads();
#pragma unroll
    for (int i = 0; i < 4; i++) {
        const int n = n0 + ty + i * 8;
        const float is = 1.0f / sb[n];
        out[(size_t)n * Kdim + k0 + tx] = q8(t[tx][ty + i * 8], is);
    }
}

// ============================================================================
// int8 IMMA GEMM: C[M,N] = (sa_r*sb_c)*(A8[M,K] @ B8t[N,K]^T) + bias (+res)
// 128x128 CTA tile, BK=64 (bytes), 256 threads (8 warps, 32x64 warp tiles),
// 3-stage cp.async ring (R5-validated schedule).
// ============================================================================
#define S8_STR 80                        // 64B row + 16B pad (conflict-free)
#define S8_TILE (128 * S8_STR)           // 10240 B per operand per stage
#define S8_STAGE (2 * S8_TILE)           // 20480
#define GEMM_SMEM_BYTES (3 * S8_STAGE)   // 61440

template<bool QKV>
__global__ __launch_bounds__(256)
void gemm_s8_kernel(const int8_t* __restrict__ A, const float* __restrict__ sa,
                    const int8_t* __restrict__ Bt, const float* __restrict__ sb,
                    const float* __restrict__ bias, const float* __restrict__ res,
                    void* __restrict__ Cout, int K, int N)
{
    extern __shared__ __align__(16) uint8_t sh8[];
    const uint32_t sbase = smem_u32(sh8);

    const int tid = threadIdx.x;
    const int w = tid >> 5, lane = tid & 31;
    const int g = lane >> 2, tig = lane & 3;
    const int wm = w >> 1, wn = w & 1;
    const int bm = blockIdx.y * 128, bn = blockIdx.x * 128;
    const int nst = K / 64;   // 16

    int cf[2][8][4];
#pragma unroll
    for (int mi = 0; mi < 2; mi++)
#pragma unroll
        for (int ni = 0; ni < 8; ni++)
#pragma unroll
            for (int q = 0; q < 4; q++) cf[mi][ni][q] = 0;

    auto load_stage = [&](int st, int ks) {
        const uint32_t ab = sbase + st * S8_STAGE;
        const uint32_t bb = ab + S8_TILE;
#pragma unroll
        for (int i = 0; i < 2; i++) {
            int l = tid + i * 256;
            int row = l >> 2, seg = l & 3;
            cpasync16(ab + row * S8_STR + seg * 16,
                      A + (size_t)(bm + row) * K + ks * 64 + seg * 16);
        }
#pragma unroll
        for (int i = 0; i < 2; i++) {
            int l = tid + i * 256;
            int row = l >> 2, seg = l & 3;
            cpasync16(bb + row * S8_STR + seg * 16,
                      Bt + (size_t)(bn + row) * K + ks * 64 + seg * 16);
        }
    };

    load_stage(0, 0); CP_COMMIT();
    load_stage(1, 1); CP_COMMIT();
    load_stage(2, 2); CP_COMMIT();

    const int l16 = lane & 15;
    const int hib = (lane >> 4) * 16;                    // A high-16B select
    const int brow = ((lane >> 4) << 3) + (lane & 7);    // B row select
    const int bhib = ((lane >> 3) & 1) * 16;             // B 16B select

    for (int ks = 0; ks < nst; ks++) {
        if (ks <= nst - 3)      { CP_WAIT2(); }
        else if (ks == nst - 2) { CP_WAIT1(); }
        else                    { CP_WAIT0(); }
        __syncthreads();

        const int st = ks % 3;
        const uint32_t ab = sbase + st * S8_STAGE;
        const uint32_t bb = ab + S8_TILE;
#pragma unroll
        for (int kc = 0; kc < 2; kc++) {
            uint32_t au[2][4];
#pragma unroll
            for (int mi = 0; mi < 2; mi++)
                ldmatrix_x4(au[mi], ab + (wm * 32 + mi * 16 + l16) * S8_STR
                                     + kc * 32 + hib);
            uint32_t bu[8][2];
#pragma unroll
            for (int p = 0; p < 4; p++) {
                uint32_t t4[4];
                ldmatrix_x4(t4, bb + (wn * 64 + p * 16 + brow) * S8_STR
                                 + kc * 32 + bhib);
                bu[2 * p][0] = t4[0]; bu[2 * p][1] = t4[1];
                bu[2 * p + 1][0] = t4[2]; bu[2 * p + 1][1] = t4[3];
            }
#pragma unroll
            for (int mi = 0; mi < 2; mi++)
#pragma unroll
                for (int ni = 0; ni < 8; ni++)
                    mma_s8(cf[mi][ni], au[mi], bu[ni]);
        }

        if (ks + 3 < nst) { load_stage((ks + 3) % 3, ks + 3); CP_COMMIT(); }
    }

    // epilogue: dequant + bias (+res / QKV post)
#pragma unroll
    for (int mi = 0; mi < 2; mi++) {
        const int r = bm + wm * 32 + mi * 16 + g;
        const float sa0 = sa[r], sa1 = sa[r + 8];
#pragma unroll
        for (int ni = 0; ni < 8; ni++) {
            const int c = bn + wn * 64 + ni * 8 + 2 * tig;
            const float sb0 = sb[c], sb1 = sb[c + 1];
            float v0 = (float)cf[mi][ni][0] * sa0 * sb0 + bias[c];
            float v1 = (float)cf[mi][ni][1] * sa0 * sb1 + bias[c + 1];
            float v2 = (float)cf[mi][ni][2] * sa1 * sb0 + bias[c];
            float v3 = (float)cf[mi][ni][3] * sa1 * sb1 + bias[c + 1];
            if (QKV) {
                if ((c % 192) < 64) { v0 *= 0.125f; v1 *= 0.125f; v2 *= 0.125f; v3 *= 0.125f; }
                __nv_bfloat16* Cb = (__nv_bfloat16*)Cout;
                *(uint32_t*)(Cb + (size_t)r * N + c) = pack_bf16(v0, v1);
                *(uint32_t*)(Cb + (size_t)(r + 8) * N + c) = pack_bf16(v2, v3);
            } else {
                float* Cf = (float*)Cout;
                const float2 r0 = *(const float2*)(res + (size_t)r * N + c);
                const float2 r1 = *(const float2*)(res + (size_t)(r + 8) * N + c);
                *(float2*)(Cf + (size_t)r * N + c) = make_float2(v0 + r0.x, v1 + r0.y);
                *(float2*)(Cf + (size_t)(r + 8) * N + c) = make_float2(v2 + r1.x, v3 + r1.y);
            }
        }
    }
}

// ============================================================================
// Flash attention (R5 best config): bf16 MMA, register softmax, 4-stage KV
// ring, load issued after PV compute.
// ============================================================================
#define TS 72
#define ATTN_Q_ELE (128 * TS)
#define ATTN_KV_ELE (64 * TS)
#define ATTN_STAGE_ELE (2 * ATTN_KV_ELE)
#define ATTN_SMEM_BYTES ((ATTN_Q_ELE + 4 * ATTN_STAGE_ELE) * 2)  // 92160

__global__ __launch_bounds__(256)
void attn_bf16_kernel(const __nv_bfloat16* __restrict__ qkv,
                      __nv_bfloat16* __restrict__ ctx)
{
    extern __shared__ __align__(16) __nv_bfloat16 sha[];
    __nv_bfloat16* Qs = sha;
    __nv_bfloat16* KV = sha + ATTN_Q_ELE;

    const int bh = blockIdx.x, qt = blockIdx.y;
    const int b = bh >> 4, h = bh & 15;
    const __nv_bfloat16* base = qkv + (size_t)b * SS * NQKV + h * (3 * HDIM);

    const int tid = threadIdx.x;
    const int w = tid >> 5, lane = tid & 31;
    const int g = lane >> 2, tig = lane & 3;
    const int l16 = lane & 15;
    const int lhi = (lane >> 4) * 8;

    auto load_kv = [&](int kt, int st) {
        __nv_bfloat16* Ks = KV + st * ATTN_STAGE_ELE;
        __nv_bfloat16* Vs = Ks + ATTN_KV_ELE;
#pragma unroll
        for (int i = 0; i < 2; i++) {
            int l = tid + i * 256;
            int row = l >> 3, seg = l & 7;
            const __nv_bfloat16* gp = base + (size_t)(kt * 64 + row) * NQKV + seg * 8;
            cpasync16(smem_u32(Ks + row * TS + seg * 8), gp + HDIM);
            cpasync16(smem_u32(Vs + row * TS + seg * 8), gp + 2 * HDIM);
        }
    };

#pragma unroll
    for (int i = 0; i < 4; i++) {
        int l = tid + i * 256;
        int row = l >> 3, seg = l & 7;
        cpasync16(smem_u32(Qs + row * TS + seg * 8),
                  base + (size_t)(qt * 128 + row) * NQKV + seg * 8);
    }
    load_kv(0, 0); CP_COMMIT();
    load_kv(1, 1); CP_COMMIT();
    load_kv(2, 2); CP_COMMIT();

    uint32_t qf[4][4];
    float o[8][4];
#pragma unroll
    for (int ni = 0; ni < 8; ni++)
#pragma unroll
        for (int q = 0; q < 4; q++) o[ni][q] = 0.0f;
    float m_lo = -1e30f, m_hi = -1e30f, l_lo = 0.0f, l_hi = 0.0f;

    for (int kt = 0; kt < 32; kt++) {
        if (kt <= 29)      { CP_WAIT2(); }
        else if (kt == 30) { CP_WAIT1(); }
        else               { CP_WAIT0(); }
        __syncthreads();

        if (kt == 0) {
#pragma unroll
            for (int kc = 0; kc < 4; kc++)
                ldmatrix_x4(qf[kc], smem_u32(Qs + (w * 16 + l16) * TS + kc * 16 + lhi));
        }

        const int st = kt & 3;
        const __nv_bfloat16* Kb = KV + st * ATTN_STAGE_ELE;
        const __nv_bfloat16* Vb = Kb + ATTN_KV_ELE;

        float sfr[8][4];
#pragma unroll
        for (int ni = 0; ni < 8; ni++)
#pragma unroll
            for (int q = 0; q < 4; q++) sfr[ni][q] = 0.0f;
#pragma unroll
        for (int kc = 0; kc < 4; kc++) {
#pragma unroll
            for (int p = 0; p < 4; p++) {
                uint32_t t4[4];
                uint32_t addr = smem_u32(Kb + (p * 16 + ((lane >> 4) << 3) + (lane & 7)) * TS
                                         + kc * 16 + (((lane >> 3) & 1) << 3));
                ldmatrix_x4(t4, addr);
                mma_bf16(sfr[2 * p],     qf[kc], &t4[0]);
                mma_bf16(sfr[2 * p + 1], qf[kc], &t4[2]);
            }
        }

        float tl = -1e30f, th = -1e30f;
#pragma unroll
        for (int ni = 0; ni < 8; ni++) {
            tl = fmaxf(tl, fmaxf(sfr[ni][0], sfr[ni][1]));
            th = fmaxf(th, fmaxf(sfr[ni][2], sfr[ni][3]));
        }
        tl = fmaxf(tl, __shfl_xor_sync(0xffffffffu, tl, 1));
        tl = fmaxf(tl, __shfl_xor_sync(0xffffffffu, tl, 2));
        th = fmaxf(th, __shfl_xor_sync(0xffffffffu, th, 1));
        th = fmaxf(th, __shfl_xor_sync(0xffffffffu, th, 2));

        float mnl = fmaxf(m_lo, tl), mnh = fmaxf(m_hi, th);
        float al = __expf(m_lo - mnl), ah = __expf(m_hi - mnh);
        m_lo = mnl; m_hi = mnh;

        float sl = 0.0f, shi = 0.0f;
#pragma unroll
        for (int ni = 0; ni < 8; ni++) {
            sfr[ni][0] = __expf(sfr[ni][0] - m_lo);
            sfr[ni][1] = __expf(sfr[ni][1] - m_lo);
            sfr[ni][2] = __expf(sfr[ni][2] - m_hi);
            sfr[ni][3] = __expf(sfr[ni][3] - m_hi);
            sl  += sfr[ni][0] + sfr[ni][1];
            shi += sfr[ni][2] + sfr[ni][3];
        }
        l_lo = l_lo * al + sl;
        l_hi = l_hi * ah + shi;
#pragma unroll
        for (int ni = 0; ni < 8; ni++) {
            o[ni][0] *= al; o[ni][1] *= al;
            o[ni][2] *= ah; o[ni][3] *= ah;
        }

        uint32_t pu[4][4];
#pragma unroll
        for (int j = 0; j < 4; j++) {
            pu[j][0] = pack_bf16(sfr[2 * j][0],     sfr[2 * j][1]);
            pu[j][1] = pack_bf16(sfr[2 * j][2],     sfr[2 * j][3]);
            pu[j][2] = pack_bf16(sfr[2 * j + 1][0], sfr[2 * j + 1][1]);
            pu[j][3] = pack_bf16(sfr[2 * j + 1][2], sfr[2 * j + 1][3]);
        }

#pragma unroll
        for (int kc = 0; kc < 4; kc++) {
#pragma unroll
            for (int p = 0; p < 4; p++) {
                uint32_t t4[4];
                ldmatrix_x4t(t4, smem_u32(Vb + (kc * 16 + l16) * TS + p * 16 + lhi));
                mma_bf16(o[2 * p],     pu[kc], &t4[0]);
                mma_bf16(o[2 * p + 1], pu[kc], &t4[2]);
            }
        }

        if (kt + 3 < 32) { load_kv(kt + 3, (kt + 3) & 3); CP_COMMIT(); }
    }

    l_lo += __shfl_xor_sync(0xffffffffu, l_lo, 1);
    l_lo += __shfl_xor_sync(0xffffffffu, l_lo, 2);
    l_hi += __shfl_xor_sync(0xffffffffu, l_hi, 1);
    l_hi += __shfl_xor_sync(0xffffffffu, l_hi, 2);
    const float il = 1.0f / l_lo, ih = 1.0f / l_hi;

    const int row0 = b * SS + qt * 128 + w * 16 + g;
#pragma unroll
    for (int ni = 0; ni < 8; ni++) {
        const int col = h * HDIM + ni * 8 + 2 * tig;
        *(uint32_t*)(ctx + (size_t)row0 * HH + col) =
            pack_bf16(o[ni][0] * il, o[ni][1] * il);
        *(uint32_t*)(ctx + (size_t)(row0 + 8) * HH + col) =
            pack_bf16(o[ni][2] * ih, o[ni][3] * ih);
    }
}

// ============================================================================
// LayerNorm, single-pass (sum + sumsq together, shuffle reductions)
// ============================================================================
__global__ __launch_bounds__(256)
void layernorm_kernel(const float* __restrict__ x, const float* __restrict__ gamma,
                      const float* __restrict__ beta, float* __restrict__ out)
{
    __shared__ float2 wred[8];
    const int row = blockIdx.x;
    const int tid = threadIdx.x;

    const float4 v = ((const float4*)(x + (size_t)row * HH))[tid];
    float s  = v.x + v.y + v.z + v.w;
    float s2 = v.x * v.x + v.y * v.y + v.z * v.z + v.w * v.w;
#pragma unroll
    for (int o = 16; o > 0; o >>= 1) {
        s  += __shfl_xor_sync(~0u, s, o);
        s2 += __shfl_xor_sync(~0u, s2, o);
    }
    if ((tid & 31) == 0) wred[tid >> 5] = make_float2(s, s2);
    __syncthreads();
    s = 0.0f; s2 = 0.0f;
#pragma unroll
    for (int i = 0; i < 8; i++) { s += wred[i].x; s2 += wred[i].y; }
    const float mu = s * (1.0f / HH);
    const float var = s2 * (1.0f / HH) - mu * mu;
    const float rstd = rsqrtf(var + 1e-5f);

    const float4 gm = ((const float4*)gamma)[tid];
    const float4 bt = ((const float4*)beta)[tid];
    float4 o;
    o.x = (v.x - mu) * rstd * gm.x + bt.x;
    o.y = (v.y - mu) * rstd * gm.y + bt.y;
    o.z = (v.z - mu) * rstd * gm.z + bt.z;
    o.w = (v.w - mu) * rstd * gm.w + bt.w;
    ((float4*)(out + (size_t)row * HH))[tid] = o;
}

// ============================================================================
extern "C" void kernel_launch(void* const* d_in, const int* in_sizes, int n_in,
                              void* d_out, int out_size)
{
    const float* hidden  = (const float*)d_in[0];
    const float* w_qkv   = (const float*)d_in[1];
    const float* b_qkv   = (const float*)d_in[2];
    const float* w_dense = (const float*)d_in[3];
    const float* b_dense = (const float*)d_in[4];
    const float* gamma   = (const float*)d_in[5];
    const float* beta    = (const float*)d_in[6];
    float* out = (float*)d_out;

    __nv_bfloat16 *qkv, *ctx;
    float *x, *saA, *saC, *sbq, *sbd, *partq, *partd;
    int8_t *A8, *C8, *Bq8, *Bd8;
    cudaGetSymbolAddress((void**)&qkv,   g_qkv_bf);
    cudaGetSymbolAddress((void**)&ctx,   g_ctx_bf);
    cudaGetSymbolAddress((void**)&x,     g_x);
    cudaGetSymbolAddress((void**)&A8,    g_A8);
    cudaGetSymbolAddress((void**)&C8,    g_C8);
    cudaGetSymbolAddress((void**)&Bq8,   g_Bq8);
    cudaGetSymbolAddress((void**)&Bd8,   g_Bd8);
    cudaGetSymbolAddress((void**)&saA,   g_saA);
    cudaGetSymbolAddress((void**)&saC,   g_saC);
    cudaGetSymbolAddress((void**)&sbq,   g_sbq);
    cudaGetSymbolAddress((void**)&sbd,   g_sbd);
    cudaGetSymbolAddress((void**)&partq, g_partq);
    cudaGetSymbolAddress((void**)&partd, g_partd);

    // 0) quantization prep
    quantA_f32_kernel<<<MTOT, 256>>>(hidden, A8, saA);
    colmax_part_kernel<<<dim3(NQKV / 256, 16), 256>>>(w_qkv, partq, NQKV);
    colmax_part_kernel<<<dim3(HH / 256, 16), 256>>>(w_dense, partd, HH);
    colmax_fin_kernel<<<NQKV / 256, 256>>>(partq, sbq, NQKV);
    colmax_fin_kernel<<<HH / 256, 256>>>(partd, sbd, HH);
    quantB_T_kernel<<<dim3(NQKV / 32, HH / 32), dim3(32, 8)>>>(w_qkv, sbq, Bq8, HH, NQKV);
    quantB_T_kernel<<<dim3(HH / 32, HH / 32), dim3(32, 8)>>>(w_dense, sbd, Bd8, HH, HH);

    // 1) QKV projection (int8 IMMA) -> bf16, Q pre-scaled 1/8
    cudaFuncSetAttribute(gemm_s8_kernel<true>,
                         cudaFuncAttributeMaxDynamicSharedMemorySize, GEMM_SMEM_BYTES);
    gemm_s8_kernel<true><<<dim3(NQKV / 128, MTOT / 128), 256, GEMM_SMEM_BYTES>>>(
        A8, saA, Bq8, sbq, b_qkv, nullptr, qkv, HH, NQKV);

    // 2) Flash attention (bf16 MMA)
    cudaFuncSetAttribute(attn_bf16_kernel,
                         cudaFuncAttributeMaxDynamicSharedMemorySize, ATTN_SMEM_BYTES);
    attn_bf16_kernel<<<dim3(32, 16), 256, ATTN_SMEM_BYTES>>>(qkv, ctx);

    // 3) quantize ctx, dense projection (int8 IMMA) + bias + residual -> fp32
    quantA_bf16_kernel<<<MTOT, 256>>>(ctx, C8, saC);
    cudaFuncSetAttribute(gemm_s8_kernel<false>,
                         cudaFuncAttributeMaxDynamicSharedMemorySize, GEMM_SMEM_BYTES);
    gemm_s8_kernel<false><<<dim3(HH / 128, MTOT / 128), 256, GEMM_SMEM_BYTES>>>(
        C8, saC, Bd8, sbd, b_dense, hidden, x, HH, HH);

    // 4) LayerNorm
    layernorm_kernel<<<MTOT, 256>>>(x, gamma, beta, out);
}

// round 9
// speedup vs baseline: 1.4676x; 1.4676x over previous
#include <cuda_runtime.h>
#include <cuda_fp16.h>
#include <cstdint>
#include <math.h>

#define BB 2
#define SS 2048
#define HH 1024
#define NHEADS 16
#define HDIM 64
#define MTOT (BB*SS)      // 4096
#define NQKV (3*HH)       // 3072

// Scratch (allocation-free rule: __device__ globals)
__device__ __half g_hid_h[(size_t)MTOT * HH];    // 8 MiB
__device__ __half g_wq_h[(size_t)HH * NQKV];     // 6 MiB
__device__ __half g_wd_h[(size_t)HH * HH];       // 2 MiB
__device__ __half g_qkv_h[(size_t)MTOT * NQKV];  // 24 MiB (Q pre-scaled 1/8)
__device__ __half g_ctx_h[(size_t)MTOT * HH];    // 8 MiB
__device__ float g_x[(size_t)MTOT * HH];         // 16 MiB

// ============================================================================
// helpers
// ============================================================================
__device__ __forceinline__ uint32_t smem_u32(const void* p) {
    uint32_t a;
    asm("{ .reg .u64 t; cvta.to.shared.u64 t, %1; cvt.u32.u64 %0, t; }"
        : "=r"(a) : "l"(p));
    return a;
}
__device__ __forceinline__ void cpasync16(uint32_t s, const void* g) {
    asm volatile("cp.async.cg.shared.global [%0], [%1], 16;" :: "r"(s), "l"(g));
}
#define CP_COMMIT() asm volatile("cp.async.commit_group;" ::: "memory")
#define CP_WAIT0()  asm volatile("cp.async.wait_group 0;" ::: "memory")
#define CP_WAIT1()  asm volatile("cp.async.wait_group 1;" ::: "memory")
#define CP_WAIT2()  asm volatile("cp.async.wait_group 2;" ::: "memory")

// pack two f32 -> f16x2 (lo = first arg, hi = second arg)
__device__ __forceinline__ uint32_t pack_f16(float lo, float hi) {
    uint32_t r;
    asm("cvt.rn.f16x2.f32 %0, %1, %2;" : "=r"(r) : "f"(hi), "f"(lo));
    return r;
}

// fp16 m16n8k16, fp32 accumulate (attention)
__device__ __forceinline__ void mma_f16_f32(float c[4], const uint32_t a[4],
                                            const uint32_t b[2]) {
    asm volatile(
        "mma.sync.aligned.m16n8k16.row.col.f32.f16.f16.f32 "
        "{%0,%1,%2,%3}, {%4,%5,%6,%7}, {%8,%9}, {%0,%1,%2,%3};\n"
        : "+f"(c[0]), "+f"(c[1]), "+f"(c[2]), "+f"(c[3])
        : "r"(a[0]), "r"(a[1]), "r"(a[2]), "r"(a[3]), "r"(b[0]), "r"(b[1]));
}
// fp16 m16n8k16, fp16 accumulate (projection GEMMs inner loop)
__device__ __forceinline__ void mma_f16_f16(uint32_t c[2], const uint32_t a[4],
                                            const uint32_t b[2]) {
    asm volatile(
        "mma.sync.aligned.m16n8k16.row.col.f16.f16.f16.f16 "
        "{%0,%1}, {%2,%3,%4,%5}, {%6,%7}, {%0,%1};\n"
        : "+r"(c[0]), "+r"(c[1])
        : "r"(a[0]), "r"(a[1]), "r"(a[2]), "r"(a[3]), "r"(b[0]), "r"(b[1]));
}
__device__ __forceinline__ void ldmatrix_x4(uint32_t r[4], uint32_t addr) {
    asm volatile("ldmatrix.sync.aligned.m8n8.x4.shared.b16 {%0,%1,%2,%3}, [%4];"
                 : "=r"(r[0]), "=r"(r[1]), "=r"(r[2]), "=r"(r[3]) : "r"(addr));
}
__device__ __forceinline__ void ldmatrix_x4t(uint32_t r[4], uint32_t addr) {
    asm volatile("ldmatrix.sync.aligned.m8n8.x4.trans.shared.b16 {%0,%1,%2,%3}, [%4];"
                 : "=r"(r[0]), "=r"(r[1]), "=r"(r[2]), "=r"(r[3]) : "r"(addr));
}

// ============================================================================
// prep: fp32 -> fp16 convert
// ============================================================================
__global__ __launch_bounds__(256)
void f2h_kernel(const float* __restrict__ in, __half* __restrict__ out) {
    size_t i = (size_t)blockIdx.x * 256 + threadIdx.x;
    float4 v = ((const float4*)in)[i];
    uint2 o;
    o.x = pack_f16(v.x, v.y);
    o.y = pack_f16(v.z, v.w);
    ((uint2*)out)[i] = o;
}

// ============================================================================
// fp16 MMA GEMM with fp16 stage-accumulators promoted to fp32 each BK=64
// stage (limits fp16 add-chain to 64). 128x128 CTA tile, 256 threads
// (8 warps, 32x64 warp tiles), 3-stage cp.async ring.
// QKV variant: out fp16, +bias, Q cols (c%192<64) scaled by 0.125.
// Dense variant: out fp32, +bias, +residual.
// ============================================================================
#define AS_STR 72
#define BS_STR 136
#define AS_ELE (128 * AS_STR)
#define BS_ELE (64 * BS_STR)
#define STAGE_ELE (AS_ELE + BS_ELE)
#define GEMM_SMEM_BYTES (3 * STAGE_ELE * 2)   // 107520

template<bool QKV>
__global__ __launch_bounds__(256)
void gemm_f16_kernel(const __half* __restrict__ A,
                     const __half* __restrict__ B,
                     const float* __restrict__ bias, const float* __restrict__ res,
                     void* __restrict__ Cout, int K, int N)
{
    extern __shared__ __align__(16) __half sh[];

    const int tid = threadIdx.x;
    const int w = tid >> 5, lane = tid & 31;
    const int g = lane >> 2, tig = lane & 3;
    const int wm = w >> 1, wn = w & 1;
    const int bm = blockIdx.y * 128, bn = blockIdx.x * 128;
    const int nst = K / 64;

    float cf[2][8][4];      // fp32 master accumulators
#pragma unroll
    for (int mi = 0; mi < 2; mi++)
#pragma unroll
        for (int ni = 0; ni < 8; ni++)
#pragma unroll
            for (int q = 0; q < 4; q++) cf[mi][ni][q] = 0.0f;

    auto load_stage = [&](int st, int ks) {
        __half* As = sh + st * STAGE_ELE;
        __half* Bs = As + AS_ELE;
#pragma unroll
        for (int i = 0; i < 4; i++) {
            int l = tid + i * 256;
            int row = l >> 3, seg = l & 7;
            cpasync16(smem_u32(As + row * AS_STR + seg * 8),
                      A + (size_t)(bm + row) * K + ks * 64 + seg * 8);
        }
#pragma unroll
        for (int i = 0; i < 4; i++) {
            int l = tid + i * 256;
            int row = l >> 4, seg = l & 15;
            cpasync16(smem_u32(Bs + row * BS_STR + seg * 8),
                      B + (size_t)(ks * 64 + row) * N + bn + seg * 8);
        }
    };

    load_stage(0, 0); CP_COMMIT();
    load_stage(1, 1); CP_COMMIT();
    load_stage(2, 2); CP_COMMIT();

    const int l16 = lane & 15;
    const int lhi = (lane >> 4) * 8;

    for (int ks = 0; ks < nst; ks++) {
        if (ks <= nst - 3)      { CP_WAIT2(); }
        else if (ks == nst - 2) { CP_WAIT1(); }
        else                    { CP_WAIT0(); }
        __syncthreads();

        const int st = ks % 3;
        const __half* Ab = sh + st * STAGE_ELE;
        const __half* Bb = Ab + AS_ELE;

        // fp16 stage accumulators (zeroed each stage; chain length = 4 MMAs)
        uint32_t ch[2][8][2];
#pragma unroll
        for (int mi = 0; mi < 2; mi++)
#pragma unroll
            for (int ni = 0; ni < 8; ni++) { ch[mi][ni][0] = 0u; ch[mi][ni][1] = 0u; }

#pragma unroll
        for (int kc = 0; kc < 4; kc++) {
            uint32_t au[2][4];
#pragma unroll
            for (int mi = 0; mi < 2; mi++)
                ldmatrix_x4(au[mi], smem_u32(Ab + (wm * 32 + mi * 16 + l16) * AS_STR
                                             + kc * 16 + lhi));
            uint32_t bu[8][2];
#pragma unroll
            for (int p = 0; p < 4; p++) {
                uint32_t t4[4];
                ldmatrix_x4t(t4, smem_u32(Bb + (kc * 16 + l16) * BS_STR
                                          + wn * 64 + p * 16 + lhi));
                bu[2 * p][0] = t4[0]; bu[2 * p][1] = t4[1];
                bu[2 * p + 1][0] = t4[2]; bu[2 * p + 1][1] = t4[3];
            }
#pragma unroll
            for (int mi = 0; mi < 2; mi++)
#pragma unroll
                for (int ni = 0; ni < 8; ni++)
                    mma_f16_f16(ch[mi][ni], au[mi], bu[ni]);
        }

        // promote stage sums into fp32 accumulators
#pragma unroll
        for (int mi = 0; mi < 2; mi++)
#pragma unroll
            for (int ni = 0; ni < 8; ni++) {
                const float2 f0 = __half22float2(*(const __half2*)&ch[mi][ni][0]);
                const float2 f1 = __half22float2(*(const __half2*)&ch[mi][ni][1]);
                cf[mi][ni][0] += f0.x; cf[mi][ni][1] += f0.y;
                cf[mi][ni][2] += f1.x; cf[mi][ni][3] += f1.y;
            }

        if (ks + 3 < nst) { load_stage((ks + 3) % 3, ks + 3); CP_COMMIT(); }
    }

    // epilogue
#pragma unroll
    for (int mi = 0; mi < 2; mi++) {
        const int r = bm + wm * 32 + mi * 16 + g;
#pragma unroll
        for (int ni = 0; ni < 8; ni++) {
            const int c = bn + wn * 64 + ni * 8 + 2 * tig;
            float v0 = cf[mi][ni][0] + bias[c];
            float v1 = cf[mi][ni][1] + bias[c + 1];
            float v2 = cf[mi][ni][2] + bias[c];
            float v3 = cf[mi][ni][3] + bias[c + 1];
            if (QKV) {
                if ((c % 192) < 64) { v0 *= 0.125f; v1 *= 0.125f; v2 *= 0.125f; v3 *= 0.125f; }
                __half* Ch = (__half*)Cout;
                *(uint32_t*)(Ch + (size_t)r * N + c) = pack_f16(v0, v1);
                *(uint32_t*)(Ch + (size_t)(r + 8) * N + c) = pack_f16(v2, v3);
            } else {
                float* Cf = (float*)Cout;
                const float2 r0 = *(const float2*)(res + (size_t)r * N + c);
                const float2 r1 = *(const float2*)(res + (size_t)(r + 8) * N + c);
                *(float2*)(Cf + (size_t)r * N + c) = make_float2(v0 + r0.x, v1 + r0.y);
                *(float2*)(Cf + (size_t)(r + 8) * N + c) = make_float2(v2 + r1.x, v3 + r1.y);
            }
        }
    }
}

// ============================================================================
// Flash attention (R5-proven structure): fp16 MMA with fp32 accum, register
// softmax, 4-stage KV ring, load issued after PV compute.
// ============================================================================
#define TS 72
#define ATTN_Q_ELE (128 * TS)
#define ATTN_KV_ELE (64 * TS)
#define ATTN_STAGE_ELE (2 * ATTN_KV_ELE)
#define ATTN_SMEM_BYTES ((ATTN_Q_ELE + 4 * ATTN_STAGE_ELE) * 2)  // 92160

__global__ __launch_bounds__(256)
void attn_f16_kernel(const __half* __restrict__ qkv, __half* __restrict__ ctx)
{
    extern __shared__ __align__(16) __half sha[];
    __half* Qs = sha;
    __half* KV = sha + ATTN_Q_ELE;

    const int bh = blockIdx.x, qt = blockIdx.y;
    const int b = bh >> 4, h = bh & 15;
    const __half* base = qkv + (size_t)b * SS * NQKV + h * (3 * HDIM);

    const int tid = threadIdx.x;
    const int w = tid >> 5, lane = tid & 31;
    const int g = lane >> 2, tig = lane & 3;
    const int l16 = lane & 15;
    const int lhi = (lane >> 4) * 8;

    auto load_kv = [&](int kt, int st) {
        __half* Ks = KV + st * ATTN_STAGE_ELE;
        __half* Vs = Ks + ATTN_KV_ELE;
#pragma unroll
        for (int i = 0; i < 2; i++) {
            int l = tid + i * 256;
            int row = l >> 3, seg = l & 7;
            const __half* gp = base + (size_t)(kt * 64 + row) * NQKV + seg * 8;
            cpasync16(smem_u32(Ks + row * TS + seg * 8), gp + HDIM);
            cpasync16(smem_u32(Vs + row * TS + seg * 8), gp + 2 * HDIM);
        }
    };

#pragma unroll
    for (int i = 0; i < 4; i++) {
        int l = tid + i * 256;
        int row = l >> 3, seg = l & 7;
        cpasync16(smem_u32(Qs + row * TS + seg * 8),
                  base + (size_t)(qt * 128 + row) * NQKV + seg * 8);
    }
    load_kv(0, 0); CP_COMMIT();
    load_kv(1, 1); CP_COMMIT();
    load_kv(2, 2); CP_COMMIT();

    uint32_t qf[4][4];
    float o[8][4];
#pragma unroll
    for (int ni = 0; ni < 8; ni++)
#pragma unroll
        for (int q = 0; q < 4; q++) o[ni][q] = 0.0f;
    float m_lo = -1e30f, m_hi = -1e30f, l_lo = 0.0f, l_hi = 0.0f;

    for (int kt = 0; kt < 32; kt++) {
        if (kt <= 29)      { CP_WAIT2(); }
        else if (kt == 30) { CP_WAIT1(); }
        else               { CP_WAIT0(); }
        __syncthreads();

        if (kt == 0) {
#pragma unroll
            for (int kc = 0; kc < 4; kc++)
                ldmatrix_x4(qf[kc], smem_u32(Qs + (w * 16 + l16) * TS + kc * 16 + lhi));
        }

        const int st = kt & 3;
        const __half* Kb = KV + st * ATTN_STAGE_ELE;
        const __half* Vb = Kb + ATTN_KV_ELE;

        float sfr[8][4];
#pragma unroll
        for (int ni = 0; ni < 8; ni++)
#pragma unroll
            for (int q = 0; q < 4; q++) sfr[ni][q] = 0.0f;
#pragma unroll
        for (int kc = 0; kc < 4; kc++) {
#pragma unroll
            for (int p = 0; p < 4; p++) {
                uint32_t t4[4];
                uint32_t addr = smem_u32(Kb + (p * 16 + ((lane >> 4) << 3) + (lane & 7)) * TS
                                         + kc * 16 + (((lane >> 3) & 1) << 3));
                ldmatrix_x4(t4, addr);
                mma_f16_f32(sfr[2 * p],     qf[kc], &t4[0]);
                mma_f16_f32(sfr[2 * p + 1], qf[kc], &t4[2]);
            }
        }

        float tl = -1e30f, th = -1e30f;
#pragma unroll
        for (int ni = 0; ni < 8; ni++) {
            tl = fmaxf(tl, fmaxf(sfr[ni][0], sfr[ni][1]));
            th = fmaxf(th, fmaxf(sfr[ni][2], sfr[ni][3]));
        }
        tl = fmaxf(tl, __shfl_xor_sync(0xffffffffu, tl, 1));
        tl = fmaxf(tl, __shfl_xor_sync(0xffffffffu, tl, 2));
        th = fmaxf(th, __shfl_xor_sync(0xffffffffu, th, 1));
        th = fmaxf(th, __shfl_xor_sync(0xffffffffu, th, 2));

        float mnl = fmaxf(m_lo, tl), mnh = fmaxf(m_hi, th);
        float al = __expf(m_lo - mnl), ah = __expf(m_hi - mnh);
        m_lo = mnl; m_hi = mnh;

        float sl = 0.0f, shi = 0.0f;
#pragma unroll
        for (int ni = 0; ni < 8; ni++) {
            sfr[ni][0] = __expf(sfr[ni][0] - m_lo);
            sfr[ni][1] = __expf(sfr[ni][1] - m_lo);
            sfr[ni][2] = __expf(sfr[ni][2] - m_hi);
            sfr[ni][3] = __expf(sfr[ni][3] - m_hi);
            sl  += sfr[ni][0] + sfr[ni][1];
            shi += sfr[ni][2] + sfr[ni][3];
        }
        l_lo = l_lo * al + sl;
        l_hi = l_hi * ah + shi;
#pragma unroll
        for (int ni = 0; ni < 8; ni++) {
            o[ni][0] *= al; o[ni][1] *= al;
            o[ni][2] *= ah; o[ni][3] *= ah;
        }

        uint32_t pu[4][4];
#pragma unroll
        for (int j = 0; j < 4; j++) {
            pu[j][0] = pack_f16(sfr[2 * j][0],     sfr[2 * j][1]);
            pu[j][1] = pack_f16(sfr[2 * j][2],     sfr[2 * j][3]);
            pu[j][2] = pack_f16(sfr[2 * j + 1][0], sfr[2 * j + 1][1]);
            pu[j][3] = pack_f16(sfr[2 * j + 1][2], sfr[2 * j + 1][3]);
        }

#pragma unroll
        for (int kc = 0; kc < 4; kc++) {
#pragma unroll
            for (int p = 0; p < 4; p++) {
                uint32_t t4[4];
                ldmatrix_x4t(t4, smem_u32(Vb + (kc * 16 + l16) * TS + p * 16 + lhi));
                mma_f16_f32(o[2 * p],     pu[kc], &t4[0]);
                mma_f16_f32(o[2 * p + 1], pu[kc], &t4[2]);
            }
        }

        if (kt + 3 < 32) { load_kv(kt + 3, (kt + 3) & 3); CP_COMMIT(); }
    }

    l_lo += __shfl_xor_sync(0xffffffffu, l_lo, 1);
    l_lo += __shfl_xor_sync(0xffffffffu, l_lo, 2);
    l_hi += __shfl_xor_sync(0xffffffffu, l_hi, 1);
    l_hi += __shfl_xor_sync(0xffffffffu, l_hi, 2);
    const float il = 1.0f / l_lo, ih = 1.0f / l_hi;

    const int row0 = b * SS + qt * 128 + w * 16 + g;
#pragma unroll
    for (int ni = 0; ni < 8; ni++) {
        const int col = h * HDIM + ni * 8 + 2 * tig;
        *(uint32_t*)(ctx + (size_t)row0 * HH + col) =
            pack_f16(o[ni][0] * il, o[ni][1] * il);
        *(uint32_t*)(ctx + (size_t)(row0 + 8) * HH + col) =
            pack_f16(o[ni][2] * ih, o[ni][3] * ih);
    }
}

// ============================================================================
// LayerNorm, single-pass (sum + sumsq, shuffle reductions)
// ============================================================================
__global__ __launch_bounds__(256)
void layernorm_kernel(const float* __restrict__ x, const float* __restrict__ gamma,
                      const float* __restrict__ beta, float* __restrict__ out)
{
    __shared__ float2 wred[8];
    const int row = blockIdx.x;
    const int tid = threadIdx.x;

    const float4 v = ((const float4*)(x + (size_t)row * HH))[tid];
    float s  = v.x + v.y + v.z + v.w;
    float s2 = v.x * v.x + v.y * v.y + v.z * v.z + v.w * v.w;
#pragma unroll
    for (int o = 16; o > 0; o >>= 1) {
        s  += __shfl_xor_sync(~0u, s, o);
        s2 += __shfl_xor_sync(~0u, s2, o);
    }
    if ((tid & 31) == 0) wred[tid >> 5] = make_float2(s, s2);
    __syncthreads();
    s = 0.0f; s2 = 0.0f;
#pragma unroll
    for (int i = 0; i < 8; i++) { s += wred[i].x; s2 += wred[i].y; }
    const float mu = s * (1.0f / HH);
    const float var = s2 * (1.0f / HH) - mu * mu;
    const float rstd = rsqrtf(var + 1e-5f);

    const float4 gm = ((const float4*)gamma)[tid];
    const float4 bt = ((const float4*)beta)[tid];
    float4 o;
    o.x = (v.x - mu) * rstd * gm.x + bt.x;
    o.y = (v.y - mu) * rstd * gm.y + bt.y;
    o.z = (v.z - mu) * rstd * gm.z + bt.z;
    o.w = (v.w - mu) * rstd * gm.w + bt.w;
    ((float4*)(out + (size_t)row * HH))[tid] = o;
}

// ============================================================================
extern "C" void kernel_launch(void* const* d_in, const int* in_sizes, int n_in,
                              void* d_out, int out_size)
{
    const float* hidden  = (const float*)d_in[0];
    const float* w_qkv   = (const float*)d_in[1];
    const float* b_qkv   = (const float*)d_in[2];
    const float* w_dense = (const float*)d_in[3];
    const float* b_dense = (const float*)d_in[4];
    const float* gamma   = (const float*)d_in[5];
    const float* beta    = (const float*)d_in[6];
    float* out = (float*)d_out;

    __half *hid, *wq, *wd, *qkv, *ctx;
    float* x;
    cudaGetSymbolAddress((void**)&hid, g_hid_h);
    cudaGetSymbolAddress((void**)&wq,  g_wq_h);
    cudaGetSymbolAddress((void**)&wd,  g_wd_h);
    cudaGetSymbolAddress((void**)&qkv, g_qkv_h);
    cudaGetSymbolAddress((void**)&ctx, g_ctx_h);
    cudaGetSymbolAddress((void**)&x,   g_x);

    // 0) fp32 -> fp16 converts
    f2h_kernel<<<(MTOT * HH) / 1024, 256>>>(hidden, hid);
    f2h_kernel<<<(HH * NQKV) / 1024, 256>>>(w_qkv, wq);
    f2h_kernel<<<(HH * HH) / 1024, 256>>>(w_dense, wd);

    // 1) QKV projection (fp16 MMA, staged fp16->fp32 accum) -> fp16, Q/8
    cudaFuncSetAttribute(gemm_f16_kernel<true>,
                         cudaFuncAttributeMaxDynamicSharedMemorySize, GEMM_SMEM_BYTES);
    gemm_f16_kernel<true><<<dim3(NQKV / 128, MTOT / 128), 256, GEMM_SMEM_BYTES>>>(
        hid, wq, b_qkv, nullptr, qkv, HH, NQKV);

    // 2) Flash attention (fp16 MMA, fp32 accum)
    cudaFuncSetAttribute(attn_f16_kernel,
                         cudaFuncAttributeMaxDynamicSharedMemorySize, ATTN_SMEM_BYTES);
    attn_f16_kernel<<<dim3(32, 16), 256, ATTN_SMEM_BYTES>>>(qkv, ctx);

    // 3) Dense projection (fp16 MMA, staged accum) + bias + residual -> fp32
    cudaFuncSetAttribute(gemm_f16_kernel<false>,
                         cudaFuncAttributeMaxDynamicSharedMemorySize, GEMM_SMEM_BYTES);
    gemm_f16_kernel<false><<<dim3(HH / 128, MTOT / 128), 256, GEMM_SMEM_BYTES>>>(
        ctx, wd, b_dense, hidden, x, HH, HH);

    // 4) LayerNorm
    layernorm_kernel<<<MTOT, 256>>>(x, gamma, beta, out);
}

// round 10
// speedup vs baseline: 1.5658x; 1.0669x over previous
#include <cuda_runtime.h>
#include <cuda_fp16.h>
#include <cstdint>
#include <math.h>

#define BB 2
#define SS 2048
#define HH 1024
#define NHEADS 16
#define HDIM 64
#define MTOT (BB*SS)      // 4096
#define NQKV (3*HH)       // 3072

// Scratch (allocation-free rule: __device__ globals)
__device__ __half g_hid_h[(size_t)MTOT * HH];    // 8 MiB
__device__ __half g_wq_h[(size_t)HH * NQKV];     // 6 MiB
__device__ __half g_wd_h[(size_t)HH * HH];       // 2 MiB
__device__ __half g_qkv_h[(size_t)MTOT * NQKV];  // 24 MiB (Q pre-scaled 1/8)
__device__ __half g_ctx_h[(size_t)MTOT * HH];    // 8 MiB
__device__ float g_x[(size_t)MTOT * HH];         // 16 MiB

// ============================================================================
// helpers
// ============================================================================
__device__ __forceinline__ uint32_t smem_u32(const void* p) {
    uint32_t a;
    asm("{ .reg .u64 t; cvta.to.shared.u64 t, %1; cvt.u32.u64 %0, t; }"
        : "=r"(a) : "l"(p));
    return a;
}
__device__ __forceinline__ void cpasync16(uint32_t s, const void* g) {
    asm volatile("cp.async.cg.shared.global [%0], [%1], 16;" :: "r"(s), "l"(g));
}
#define CP_COMMIT() asm volatile("cp.async.commit_group;" ::: "memory")
#define CP_WAIT0()  asm volatile("cp.async.wait_group 0;" ::: "memory")
#define CP_WAIT1()  asm volatile("cp.async.wait_group 1;" ::: "memory")
#define CP_WAIT2()  asm volatile("cp.async.wait_group 2;" ::: "memory")

// pack two f32 -> f16x2 (lo = first arg, hi = second arg)
__device__ __forceinline__ uint32_t pack_f16(float lo, float hi) {
    uint32_t r;
    asm("cvt.rn.f16x2.f32 %0, %1, %2;" : "=r"(r) : "f"(hi), "f"(lo));
    return r;
}
// fp16 m16n8k16, fp32 accumulate (all GEMMs + attention)
__device__ __forceinline__ void mma_f16_f32(float c[4], const uint32_t a[4],
                                            const uint32_t b[2]) {
    asm volatile(
        "mma.sync.aligned.m16n8k16.row.col.f32.f16.f16.f32 "
        "{%0,%1,%2,%3}, {%4,%5,%6,%7}, {%8,%9}, {%0,%1,%2,%3};\n"
        : "+f"(c[0]), "+f"(c[1]), "+f"(c[2]), "+f"(c[3])
        : "r"(a[0]), "r"(a[1]), "r"(a[2]), "r"(a[3]), "r"(b[0]), "r"(b[1]));
}
__device__ __forceinline__ void ldmatrix_x4(uint32_t r[4], uint32_t addr) {
    asm volatile("ldmatrix.sync.aligned.m8n8.x4.shared.b16 {%0,%1,%2,%3}, [%4];"
                 : "=r"(r[0]), "=r"(r[1]), "=r"(r[2]), "=r"(r[3]) : "r"(addr));
}
__device__ __forceinline__ void ldmatrix_x4t(uint32_t r[4], uint32_t addr) {
    asm volatile("ldmatrix.sync.aligned.m8n8.x4.trans.shared.b16 {%0,%1,%2,%3}, [%4];"
                 : "=r"(r[0]), "=r"(r[1]), "=r"(r[2]), "=r"(r[3]) : "r"(addr));
}

// ============================================================================
// prep: fp32 -> fp16 convert
// ============================================================================
__global__ __launch_bounds__(256)
void f2h_kernel(const float* __restrict__ in, __half* __restrict__ out) {
    size_t i = (size_t)blockIdx.x * 256 + threadIdx.x;
    float4 v = ((const float4*)in)[i];
    uint2 o;
    o.x = pack_f16(v.x, v.y);
    o.y = pack_f16(v.z, v.w);
    ((uint2*)out)[i] = o;
}

// ============================================================================
// fp16 MMA GEMM (fp32 accum): 128x128 CTA tile, BK=64, 256 threads (8 warps,
// 32x64 warp tiles), 3-stage cp.async ring — exact R5-proven schedule.
// QKV variant: out fp16, +bias, Q cols (c%192<64) scaled by 0.125.
// Dense variant: out fp32, +bias, +residual.
// ============================================================================
#define AS_STR 72
#define BS_STR 136
#define AS_ELE (128 * AS_STR)
#define BS_ELE (64 * BS_STR)
#define STAGE_ELE (AS_ELE + BS_ELE)
#define GEMM_SMEM_BYTES (3 * STAGE_ELE * 2)   // 107520

template<bool QKV>
__global__ __launch_bounds__(256)
void gemm_f16_kernel(const __half* __restrict__ A,
                     const __half* __restrict__ B,
                     const float* __restrict__ bias, const float* __restrict__ res,
                     void* __restrict__ Cout, int K, int N)
{
    extern __shared__ __align__(16) __half sh[];

    const int tid = threadIdx.x;
    const int w = tid >> 5, lane = tid & 31;
    const int g = lane >> 2, tig = lane & 3;
    const int wm = w >> 1, wn = w & 1;
    const int bm = blockIdx.y * 128, bn = blockIdx.x * 128;
    const int nst = K / 64;

    float cf[2][8][4];
#pragma unroll
    for (int mi = 0; mi < 2; mi++)
#pragma unroll
        for (int ni = 0; ni < 8; ni++)
#pragma unroll
            for (int q = 0; q < 4; q++) cf[mi][ni][q] = 0.0f;

    auto load_stage = [&](int st, int ks) {
        __half* As = sh + st * STAGE_ELE;
        __half* Bs = As + AS_ELE;
#pragma unroll
        for (int i = 0; i < 4; i++) {
            int l = tid + i * 256;
            int row = l >> 3, seg = l & 7;
            cpasync16(smem_u32(As + row * AS_STR + seg * 8),
                      A + (size_t)(bm + row) * K + ks * 64 + seg * 8);
        }
#pragma unroll
        for (int i = 0; i < 4; i++) {
            int l = tid + i * 256;
            int row = l >> 4, seg = l & 15;
            cpasync16(smem_u32(Bs + row * BS_STR + seg * 8),
                      B + (size_t)(ks * 64 + row) * N + bn + seg * 8);
        }
    };

    load_stage(0, 0); CP_COMMIT();
    load_stage(1, 1); CP_COMMIT();
    load_stage(2, 2); CP_COMMIT();

    const int l16 = lane & 15;
    const int lhi = (lane >> 4) * 8;

    for (int ks = 0; ks < nst; ks++) {
        if (ks <= nst - 3)      { CP_WAIT2(); }
        else if (ks == nst - 2) { CP_WAIT1(); }
        else                    { CP_WAIT0(); }
        __syncthreads();

        const int st = ks % 3;
        const __half* Ab = sh + st * STAGE_ELE;
        const __half* Bb = Ab + AS_ELE;
#pragma unroll
        for (int kc = 0; kc < 4; kc++) {
            uint32_t au[2][4];
#pragma unroll
            for (int mi = 0; mi < 2; mi++)
                ldmatrix_x4(au[mi], smem_u32(Ab + (wm * 32 + mi * 16 + l16) * AS_STR
                                             + kc * 16 + lhi));
            uint32_t bu[8][2];
#pragma unroll
            for (int p = 0; p < 4; p++) {
                uint32_t t4[4];
                ldmatrix_x4t(t4, smem_u32(Bb + (kc * 16 + l16) * BS_STR
                                          + wn * 64 + p * 16 + lhi));
                bu[2 * p][0] = t4[0]; bu[2 * p][1] = t4[1];
                bu[2 * p + 1][0] = t4[2]; bu[2 * p + 1][1] = t4[3];
            }
#pragma unroll
            for (int mi = 0; mi < 2; mi++)
#pragma unroll
                for (int ni = 0; ni < 8; ni++)
                    mma_f16_f32(cf[mi][ni], au[mi], bu[ni]);
        }

        if (ks + 3 < nst) { load_stage((ks + 3) % 3, ks + 3); CP_COMMIT(); }
    }

    // epilogue
#pragma unroll
    for (int mi = 0; mi < 2; mi++) {
        const int r = bm + wm * 32 + mi * 16 + g;
#pragma unroll
        for (int ni = 0; ni < 8; ni++) {
            const int c = bn + wn * 64 + ni * 8 + 2 * tig;
            float v0 = cf[mi][ni][0] + bias[c];
            float v1 = cf[mi][ni][1] + bias[c + 1];
            float v2 = cf[mi][ni][2] + bias[c];
            float v3 = cf[mi][ni][3] + bias[c + 1];
            if (QKV) {
                if ((c % 192) < 64) { v0 *= 0.125f; v1 *= 0.125f; v2 *= 0.125f; v3 *= 0.125f; }
                __half* Ch = (__half*)Cout;
                *(uint32_t*)(Ch + (size_t)r * N + c) = pack_f16(v0, v1);
                *(uint32_t*)(Ch + (size_t)(r + 8) * N + c) = pack_f16(v2, v3);
            } else {
                float* Cf = (float*)Cout;
                const float2 r0 = *(const float2*)(res + (size_t)r * N + c);
                const float2 r1 = *(const float2*)(res + (size_t)(r + 8) * N + c);
                *(float2*)(Cf + (size_t)r * N + c) = make_float2(v0 + r0.x, v1 + r0.y);
                *(float2*)(Cf + (size_t)(r + 8) * N + c) = make_float2(v2 + r1.x, v3 + r1.y);
            }
        }
    }
}

// ============================================================================
// Flash attention (R5-proven structure): fp16 MMA with fp32 accum, register
// softmax, 4-stage KV ring, load issued after PV compute.
// ============================================================================
#define TS 72
#define ATTN_Q_ELE (128 * TS)
#define ATTN_KV_ELE (64 * TS)
#define ATTN_STAGE_ELE (2 * ATTN_KV_ELE)
#define ATTN_SMEM_BYTES ((ATTN_Q_ELE + 4 * ATTN_STAGE_ELE) * 2)  // 92160

__global__ __launch_bounds__(256)
void attn_f16_kernel(const __half* __restrict__ qkv, __half* __restrict__ ctx)
{
    extern __shared__ __align__(16) __half sha[];
    __half* Qs = sha;
    __half* KV = sha + ATTN_Q_ELE;

    const int bh = blockIdx.x, qt = blockIdx.y;
    const int b = bh >> 4, h = bh & 15;
    const __half* base = qkv + (size_t)b * SS * NQKV + h * (3 * HDIM);

    const int tid = threadIdx.x;
    const int w = tid >> 5, lane = tid & 31;
    const int g = lane >> 2, tig = lane & 3;
    const int l16 = lane & 15;
    const int lhi = (lane >> 4) * 8;

    auto load_kv = [&](int kt, int st) {
        __half* Ks = KV + st * ATTN_STAGE_ELE;
        __half* Vs = Ks + ATTN_KV_ELE;
#pragma unroll
        for (int i = 0; i < 2; i++) {
            int l = tid + i * 256;
            int row = l >> 3, seg = l & 7;
            const __half* gp = base + (size_t)(kt * 64 + row) * NQKV + seg * 8;
            cpasync16(smem_u32(Ks + row * TS + seg * 8), gp + HDIM);
            cpasync16(smem_u32(Vs + row * TS + seg * 8), gp + 2 * HDIM);
        }
    };

#pragma unroll
    for (int i = 0; i < 4; i++) {
        int l = tid + i * 256;
        int row = l >> 3, seg = l & 7;
        cpasync16(smem_u32(Qs + row * TS + seg * 8),
                  base + (size_t)(qt * 128 + row) * NQKV + seg * 8);
    }
    load_kv(0, 0); CP_COMMIT();
    load_kv(1, 1); CP_COMMIT();
    load_kv(2, 2); CP_COMMIT();

    uint32_t qf[4][4];
    float o[8][4];
#pragma unroll
    for (int ni = 0; ni < 8; ni++)
#pragma unroll
        for (int q = 0; q < 4; q++) o[ni][q] = 0.0f;
    float m_lo = -1e30f, m_hi = -1e30f, l_lo = 0.0f, l_hi = 0.0f;

    for (int kt = 0; kt < 32; kt++) {
        if (kt <= 29)      { CP_WAIT2(); }
        else if (kt == 30) { CP_WAIT1(); }
        else               { CP_WAIT0(); }
        __syncthreads();

        if (kt == 0) {
#pragma unroll
            for (int kc = 0; kc < 4; kc++)
                ldmatrix_x4(qf[kc], smem_u32(Qs + (w * 16 + l16) * TS + kc * 16 + lhi));
        }

        const int st = kt & 3;
        const __half* Kb = KV + st * ATTN_STAGE_ELE;
        const __half* Vb = Kb + ATTN_KV_ELE;

        float sfr[8][4];
#pragma unroll
        for (int ni = 0; ni < 8; ni++)
#pragma unroll
            for (int q = 0; q < 4; q++) sfr[ni][q] = 0.0f;
#pragma unroll
        for (int kc = 0; kc < 4; kc++) {
#pragma unroll
            for (int p = 0; p < 4; p++) {
                uint32_t t4[4];
                uint32_t addr = smem_u32(Kb + (p * 16 + ((lane >> 4) << 3) + (lane & 7)) * TS
                                         + kc * 16 + (((lane >> 3) & 1) << 3));
                ldmatrix_x4(t4, addr);
                mma_f16_f32(sfr[2 * p],     qf[kc], &t4[0]);
                mma_f16_f32(sfr[2 * p + 1], qf[kc], &t4[2]);
            }
        }

        float tl = -1e30f, th = -1e30f;
#pragma unroll
        for (int ni = 0; ni < 8; ni++) {
            tl = fmaxf(tl, fmaxf(sfr[ni][0], sfr[ni][1]));
            th = fmaxf(th, fmaxf(sfr[ni][2], sfr[ni][3]));
        }
        tl = fmaxf(tl, __shfl_xor_sync(0xffffffffu, tl, 1));
        tl = fmaxf(tl, __shfl_xor_sync(0xffffffffu, tl, 2));
        th = fmaxf(th, __shfl_xor_sync(0xffffffffu, th, 1));
        th = fmaxf(th, __shfl_xor_sync(0xffffffffu, th, 2));

        float mnl = fmaxf(m_lo, tl), mnh = fmaxf(m_hi, th);
        float al = __expf(m_lo - mnl), ah = __expf(m_hi - mnh);
        m_lo = mnl; m_hi = mnh;

        float sl = 0.0f, shi = 0.0f;
#pragma unroll
        for (int ni = 0; ni < 8; ni++) {
            sfr[ni][0] = __expf(sfr[ni][0] - m_lo);
            sfr[ni][1] = __expf(sfr[ni][1] - m_lo);
            sfr[ni][2] = __expf(sfr[ni][2] - m_hi);
            sfr[ni][3] = __expf(sfr[ni][3] - m_hi);
            sl  += sfr[ni][0] + sfr[ni][1];
            shi += sfr[ni][2] + sfr[ni][3];
        }
        l_lo = l_lo * al + sl;
        l_hi = l_hi * ah + shi;
#pragma unroll
        for (int ni = 0; ni < 8; ni++) {
            o[ni][0] *= al; o[ni][1] *= al;
            o[ni][2] *= ah; o[ni][3] *= ah;
        }

        uint32_t pu[4][4];
#pragma unroll
        for (int j = 0; j < 4; j++) {
            pu[j][0] = pack_f16(sfr[2 * j][0],     sfr[2 * j][1]);
            pu[j][1] = pack_f16(sfr[2 * j][2],     sfr[2 * j][3]);
            pu[j][2] = pack_f16(sfr[2 * j + 1][0], sfr[2 * j + 1][1]);
            pu[j][3] = pack_f16(sfr[2 * j + 1][2], sfr[2 * j + 1][3]);
        }

#pragma unroll
        for (int kc = 0; kc < 4; kc++) {
#pragma unroll
            for (int p = 0; p < 4; p++) {
                uint32_t t4[4];
                ldmatrix_x4t(t4, smem_u32(Vb + (kc * 16 + l16) * TS + p * 16 + lhi));
                mma_f16_f32(o[2 * p],     pu[kc], &t4[0]);
                mma_f16_f32(o[2 * p + 1], pu[kc], &t4[2]);
            }
        }

        if (kt + 3 < 32) { load_kv(kt + 3, (kt + 3) & 3); CP_COMMIT(); }
    }

    l_lo += __shfl_xor_sync(0xffffffffu, l_lo, 1);
    l_lo += __shfl_xor_sync(0xffffffffu, l_lo, 2);
    l_hi += __shfl_xor_sync(0xffffffffu, l_hi, 1);
    l_hi += __shfl_xor_sync(0xffffffffu, l_hi, 2);
    const float il = 1.0f / l_lo, ih = 1.0f / l_hi;

    const int row0 = b * SS + qt * 128 + w * 16 + g;
#pragma unroll
    for (int ni = 0; ni < 8; ni++) {
        const int col = h * HDIM + ni * 8 + 2 * tig;
        *(uint32_t*)(ctx + (size_t)row0 * HH + col) =
            pack_f16(o[ni][0] * il, o[ni][1] * il);
        *(uint32_t*)(ctx + (size_t)(row0 + 8) * HH + col) =
            pack_f16(o[ni][2] * ih, o[ni][3] * ih);
    }
}

// ============================================================================
// LayerNorm: ONE WARP PER ROW, pure shuffle reductions, no block barriers.
// Each lane holds 32 floats (8 float4) of its row.
// ============================================================================
__global__ __launch_bounds__(256)
void layernorm_warp_kernel(const float* __restrict__ x, const float* __restrict__ gamma,
                           const float* __restrict__ beta, float* __restrict__ out)
{
    const int w = threadIdx.x >> 5;
    const int lane = threadIdx.x & 31;
    const int row = blockIdx.x * 8 + w;

    const float4* xp = (const float4*)(x + (size_t)row * HH);
    float4 v[8];
    float s = 0.0f, s2 = 0.0f;
#pragma unroll
    for (int i = 0; i < 8; i++) {
        v[i] = xp[lane + i * 32];
        s  += v[i].x + v[i].y + v[i].z + v[i].w;
        s2 += v[i].x * v[i].x + v[i].y * v[i].y + v[i].z * v[i].z + v[i].w * v[i].w;
    }
#pragma unroll
    for (int o = 16; o > 0; o >>= 1) {
        s  += __shfl_xor_sync(~0u, s, o);
        s2 += __shfl_xor_sync(~0u, s2, o);
    }
    const float mu = s * (1.0f / HH);
    const float var = s2 * (1.0f / HH) - mu * mu;
    const float rstd = rsqrtf(var + 1e-5f);

    const float4* gp = (const float4*)gamma;
    const float4* bp = (const float4*)beta;
    float4* op = (float4*)(out + (size_t)row * HH);
#pragma unroll
    for (int i = 0; i < 8; i++) {
        const float4 gm = gp[lane + i * 32];
        const float4 bt = bp[lane + i * 32];
        float4 o;
        o.x = (v[i].x - mu) * rstd * gm.x + bt.x;
        o.y = (v[i].y - mu) * rstd * gm.y + bt.y;
        o.z = (v[i].z - mu) * rstd * gm.z + bt.z;
        o.w = (v[i].w - mu) * rstd * gm.w + bt.w;
        op[lane + i * 32] = o;
    }
}

// ============================================================================
extern "C" void kernel_launch(void* const* d_in, const int* in_sizes, int n_in,
                              void* d_out, int out_size)
{
    const float* hidden  = (const float*)d_in[0];
    const float* w_qkv   = (const float*)d_in[1];
    const float* b_qkv   = (const float*)d_in[2];
    const float* w_dense = (const float*)d_in[3];
    const float* b_dense = (const float*)d_in[4];
    const float* gamma   = (const float*)d_in[5];
    const float* beta    = (const float*)d_in[6];
    float* out = (float*)d_out;

    __half *hid, *wq, *wd, *qkv, *ctx;
    float* x;
    cudaGetSymbolAddress((void**)&hid, g_hid_h);
    cudaGetSymbolAddress((void**)&wq,  g_wq_h);
    cudaGetSymbolAddress((void**)&wd,  g_wd_h);
    cudaGetSymbolAddress((void**)&qkv, g_qkv_h);
    cudaGetSymbolAddress((void**)&ctx, g_ctx_h);
    cudaGetSymbolAddress((void**)&x,   g_x);

    // 0) fp32 -> fp16 converts (hidden + w_qkv needed before QKV GEMM)
    f2h_kernel<<<(MTOT * HH) / 1024, 256>>>(hidden, hid);
    f2h_kernel<<<(HH * NQKV) / 1024, 256>>>(w_qkv, wq);

    // 1) QKV projection (fp16 MMA, fp32 accum) -> fp16, Q pre-scaled 1/8
    cudaFuncSetAttribute(gemm_f16_kernel<true>,
                         cudaFuncAttributeMaxDynamicSharedMemorySize, GEMM_SMEM_BYTES);
    gemm_f16_kernel<true><<<dim3(NQKV / 128, MTOT / 128), 256, GEMM_SMEM_BYTES>>>(
        hid, wq, b_qkv, nullptr, qkv, HH, NQKV);

    // 1b) dense-weight convert (independent of QKV/attention results)
    f2h_kernel<<<(HH * HH) / 1024, 256>>>(w_dense, wd);

    // 2) Flash attention (fp16 MMA, fp32 accum)
    cudaFuncSetAttribute(attn_f16_kernel,
                         cudaFuncAttributeMaxDynamicSharedMemorySize, ATTN_SMEM_BYTES);
    attn_f16_kernel<<<dim3(32, 16), 256, ATTN_SMEM_BYTES>>>(qkv, ctx);

    // 3) Dense projection (fp16 MMA, fp32 accum) + bias + residual -> fp32
    cudaFuncSetAttribute(gemm_f16_kernel<false>,
                         cudaFuncAttributeMaxDynamicSharedMemorySize, GEMM_SMEM_BYTES);
    gemm_f16_kernel<false><<<dim3(HH / 128, MTOT / 128), 256, GEMM_SMEM_BYTES>>>(
        ctx, wd, b_dense, hidden, x, HH, HH);

    // 4) LayerNorm (one warp per row)
    layernorm_warp_kernel<<<MTOT / 8, 256>>>(x, gamma, beta, out);
}

// round 11
// speedup vs baseline: 1.6823x; 1.0744x over previous
#include <cuda_runtime.h>
#include <cuda_fp16.h>
#include <cstdint>
#include <math.h>

#define BB 2
#define SS 2048
#define HH 1024
#define NHEADS 16
#define HDIM 64
#define MTOT (BB*SS)      // 4096
#define NQKV (3*HH)       // 3072

// Scratch (allocation-free rule: __device__ globals)
__device__ __half g_hid_h[(size_t)MTOT * HH];    // 8 MiB
__device__ __half g_wq_h[(size_t)HH * NQKV];     // 6 MiB
__device__ __half g_wd_h[(size_t)HH * HH];       // 2 MiB
__device__ __half g_qkv_h[(size_t)MTOT * NQKV];  // 24 MiB (Q pre-scaled 1/8)
__device__ __half g_ctx_h[(size_t)MTOT * HH];    // 8 MiB
__device__ float g_x[(size_t)MTOT * HH];         // 16 MiB

// ============================================================================
// helpers
// ============================================================================
__device__ __forceinline__ uint32_t smem_u32(const void* p) {
    uint32_t a;
    asm("{ .reg .u64 t; cvta.to.shared.u64 t, %1; cvt.u32.u64 %0, t; }"
        : "=r"(a) : "l"(p));
    return a;
}
__device__ __forceinline__ void cpasync16(uint32_t s, const void* g) {
    asm volatile("cp.async.cg.shared.global [%0], [%1], 16;" :: "r"(s), "l"(g));
}
#define CP_COMMIT() asm volatile("cp.async.commit_group;" ::: "memory")
#define CP_WAIT0()  asm volatile("cp.async.wait_group 0;" ::: "memory")
#define CP_WAIT1()  asm volatile("cp.async.wait_group 1;" ::: "memory")
#define CP_WAIT2()  asm volatile("cp.async.wait_group 2;" ::: "memory")

// pack two f32 -> f16x2 (lo = first arg, hi = second arg)
__device__ __forceinline__ uint32_t pack_f16(float lo, float hi) {
    uint32_t r;
    asm("cvt.rn.f16x2.f32 %0, %1, %2;" : "=r"(r) : "f"(hi), "f"(lo));
    return r;
}
// fp16 m16n8k16, fp32 accumulate (all GEMMs + attention)
__device__ __forceinline__ void mma_f16_f32(float c[4], const uint32_t a[4],
                                            const uint32_t b[2]) {
    asm volatile(
        "mma.sync.aligned.m16n8k16.row.col.f32.f16.f16.f32 "
        "{%0,%1,%2,%3}, {%4,%5,%6,%7}, {%8,%9}, {%0,%1,%2,%3};\n"
        : "+f"(c[0]), "+f"(c[1]), "+f"(c[2]), "+f"(c[3])
        : "r"(a[0]), "r"(a[1]), "r"(a[2]), "r"(a[3]), "r"(b[0]), "r"(b[1]));
}
__device__ __forceinline__ void ldmatrix_x4(uint32_t r[4], uint32_t addr) {
    asm volatile("ldmatrix.sync.aligned.m8n8.x4.shared.b16 {%0,%1,%2,%3}, [%4];"
                 : "=r"(r[0]), "=r"(r[1]), "=r"(r[2]), "=r"(r[3]) : "r"(addr));
}
__device__ __forceinline__ void ldmatrix_x4t(uint32_t r[4], uint32_t addr) {
    asm volatile("ldmatrix.sync.aligned.m8n8.x4.trans.shared.b16 {%0,%1,%2,%3}, [%4];"
                 : "=r"(r[0]), "=r"(r[1]), "=r"(r[2]), "=r"(r[3]) : "r"(addr));
}

// ============================================================================
// prep: single-launch fp32 -> fp16 convert of all three operands
// blocks [0,4096): hidden, [4096,7168): w_qkv, [7168,8192): w_dense
// ============================================================================
__global__ __launch_bounds__(256)
void f2h_all_kernel(const float* __restrict__ hid_f, const float* __restrict__ wq_f,
                    const float* __restrict__ wd_f, __half* __restrict__ hid_h,
                    __half* __restrict__ wq_h, __half* __restrict__ wd_h)
{
    const int b = blockIdx.x;
    const float* in;
    __half* out;
    int rb;
    if (b < 4096)      { in = hid_f; out = hid_h; rb = b; }
    else if (b < 7168) { in = wq_f;  out = wq_h;  rb = b - 4096; }
    else               { in = wd_f;  out = wd_h;  rb = b - 7168; }
    const size_t i = (size_t)rb * 256 + threadIdx.x;
    const float4 v = ((const float4*)in)[i];
    uint2 o;
    o.x = pack_f16(v.x, v.y);
    o.y = pack_f16(v.z, v.w);
    ((uint2*)out)[i] = o;
}

// ============================================================================
// fp16 MMA GEMM (fp32 accum): 128x256 CTA tile, BK=64, 256 threads
// (8 warps as 2(M) x 4(N), each 64x64) — halves LDSM-per-MMA vs 32x64 tiles.
// 3-stage cp.async ring, R5-proven wait schedule.
// QKV variant: out fp16, +bias, Q cols (c%192<64) scaled by 0.125.
// Dense variant: out fp32, +bias, +residual.
// ============================================================================
#define AS_STR 72                     // 64 + 8 pad (halves)
#define BS_STR 264                    // 256 + 8 pad (halves)
#define AS_ELE (128 * AS_STR)         // 9216
#define BS_ELE (64 * BS_STR)          // 16896
#define STAGE_ELE (AS_ELE + BS_ELE)   // 26112
#define GEMM_SMEM_BYTES (3 * STAGE_ELE * 2)   // 156672

template<bool QKV>
__global__ __launch_bounds__(256)
void gemm_f16_kernel(const __half* __restrict__ A,
                     const __half* __restrict__ B,
                     const float* __restrict__ bias, const float* __restrict__ res,
                     void* __restrict__ Cout, int K, int N)
{
    extern __shared__ __align__(16) __half sh[];

    const int tid = threadIdx.x;
    const int w = tid >> 5, lane = tid & 31;
    const int g = lane >> 2, tig = lane & 3;
    const int wm = w >> 2;          // 0..1 : 64-row slab
    const int wn = w & 3;           // 0..3 : 64-col slab
    const int bm = blockIdx.y * 128, bn = blockIdx.x * 256;
    const int nst = K / 64;

    float cf[4][8][4];
#pragma unroll
    for (int mi = 0; mi < 4; mi++)
#pragma unroll
        for (int ni = 0; ni < 8; ni++)
#pragma unroll
            for (int q = 0; q < 4; q++) cf[mi][ni][q] = 0.0f;

    auto load_stage = [&](int st, int ks) {
        __half* As = sh + st * STAGE_ELE;
        __half* Bs = As + AS_ELE;
#pragma unroll
        for (int i = 0; i < 4; i++) {
            int l = tid + i * 256;
            int row = l >> 3, seg = l & 7;
            cpasync16(smem_u32(As + row * AS_STR + seg * 8),
                      A + (size_t)(bm + row) * K + ks * 64 + seg * 8);
        }
#pragma unroll
        for (int i = 0; i < 8; i++) {
            int l = tid + i * 256;
            int row = l >> 5, seg = l & 31;
            cpasync16(smem_u32(Bs + row * BS_STR + seg * 8),
                      B + (size_t)(ks * 64 + row) * N + bn + seg * 8);
        }
    };

    load_stage(0, 0); CP_COMMIT();
    load_stage(1, 1); CP_COMMIT();
    load_stage(2, 2); CP_COMMIT();

    const int l16 = lane & 15;
    const int lhi = (lane >> 4) * 8;

    for (int ks = 0; ks < nst; ks++) {
        if (ks <= nst - 3)      { CP_WAIT2(); }
        else if (ks == nst - 2) { CP_WAIT1(); }
        else                    { CP_WAIT0(); }
        __syncthreads();

        const int st = ks % 3;
        const __half* Ab = sh + st * STAGE_ELE;
        const __half* Bb = Ab + AS_ELE;
#pragma unroll
        for (int kc = 0; kc < 4; kc++) {
            uint32_t au[4][4];
#pragma unroll
            for (int mi = 0; mi < 4; mi++)
                ldmatrix_x4(au[mi], smem_u32(Ab + (wm * 64 + mi * 16 + l16) * AS_STR
                                             + kc * 16 + lhi));
            uint32_t bu[8][2];
#pragma unroll
            for (int p = 0; p < 4; p++) {
                uint32_t t4[4];
                ldmatrix_x4t(t4, smem_u32(Bb + (kc * 16 + l16) * BS_STR
                                          + wn * 64 + p * 16 + lhi));
                bu[2 * p][0] = t4[0]; bu[2 * p][1] = t4[1];
                bu[2 * p + 1][0] = t4[2]; bu[2 * p + 1][1] = t4[3];
            }
#pragma unroll
            for (int mi = 0; mi < 4; mi++)
#pragma unroll
                for (int ni = 0; ni < 8; ni++)
                    mma_f16_f32(cf[mi][ni], au[mi], bu[ni]);
        }

        if (ks + 3 < nst) { load_stage((ks + 3) % 3, ks + 3); CP_COMMIT(); }
    }

    // epilogue
#pragma unroll
    for (int mi = 0; mi < 4; mi++) {
        const int r = bm + wm * 64 + mi * 16 + g;
#pragma unroll
        for (int ni = 0; ni < 8; ni++) {
            const int c = bn + wn * 64 + ni * 8 + 2 * tig;
            float v0 = cf[mi][ni][0] + bias[c];
            float v1 = cf[mi][ni][1] + bias[c + 1];
            float v2 = cf[mi][ni][2] + bias[c];
            float v3 = cf[mi][ni][3] + bias[c + 1];
            if (QKV) {
                if ((c % 192) < 64) { v0 *= 0.125f; v1 *= 0.125f; v2 *= 0.125f; v3 *= 0.125f; }
                __half* Ch = (__half*)Cout;
                *(uint32_t*)(Ch + (size_t)r * N + c) = pack_f16(v0, v1);
                *(uint32_t*)(Ch + (size_t)(r + 8) * N + c) = pack_f16(v2, v3);
            } else {
                float* Cf = (float*)Cout;
                const float2 r0 = *(const float2*)(res + (size_t)r * N + c);
                const float2 r1 = *(const float2*)(res + (size_t)(r + 8) * N + c);
                *(float2*)(Cf + (size_t)r * N + c) = make_float2(v0 + r0.x, v1 + r0.y);
                *(float2*)(Cf + (size_t)(r + 8) * N + c) = make_float2(v2 + r1.x, v3 + r1.y);
            }
        }
    }
}

// ============================================================================
// Flash attention (R10-proven, byte-identical): fp16 MMA, fp32 accum,
// register softmax, 4-stage KV ring, load issued after PV compute.
// ============================================================================
#define TS 72
#define ATTN_Q_ELE (128 * TS)
#define ATTN_KV_ELE (64 * TS)
#define ATTN_STAGE_ELE (2 * ATTN_KV_ELE)
#define ATTN_SMEM_BYTES ((ATTN_Q_ELE + 4 * ATTN_STAGE_ELE) * 2)  // 92160

__global__ __launch_bounds__(256)
void attn_f16_kernel(const __half* __restrict__ qkv, __half* __restrict__ ctx)
{
    extern __shared__ __align__(16) __half sha[];
    __half* Qs = sha;
    __half* KV = sha + ATTN_Q_ELE;

    const int bh = blockIdx.x, qt = blockIdx.y;
    const int b = bh >> 4, h = bh & 15;
    const __half* base = qkv + (size_t)b * SS * NQKV + h * (3 * HDIM);

    const int tid = threadIdx.x;
    const int w = tid >> 5, lane = tid & 31;
    const int g = lane >> 2, tig = lane & 3;
    const int l16 = lane & 15;
    const int lhi = (lane >> 4) * 8;

    auto load_kv = [&](int kt, int st) {
        __half* Ks = KV + st * ATTN_STAGE_ELE;
        __half* Vs = Ks + ATTN_KV_ELE;
#pragma unroll
        for (int i = 0; i < 2; i++) {
            int l = tid + i * 256;
            int row = l >> 3, seg = l & 7;
            const __half* gp = base + (size_t)(kt * 64 + row) * NQKV + seg * 8;
            cpasync16(smem_u32(Ks + row * TS + seg * 8), gp + HDIM);
            cpasync16(smem_u32(Vs + row * TS + seg * 8), gp + 2 * HDIM);
        }
    };

#pragma unroll
    for (int i = 0; i < 4; i++) {
        int l = tid + i * 256;
        int row = l >> 3, seg = l & 7;
        cpasync16(smem_u32(Qs + row * TS + seg * 8),
                  base + (size_t)(qt * 128 + row) * NQKV + seg * 8);
    }
    load_kv(0, 0); CP_COMMIT();
    load_kv(1, 1); CP_COMMIT();
    load_kv(2, 2); CP_COMMIT();

    uint32_t qf[4][4];
    float o[8][4];
#pragma unroll
    for (int ni = 0; ni < 8; ni++)
#pragma unroll
        for (int q = 0; q < 4; q++) o[ni][q] = 0.0f;
    float m_lo = -1e30f, m_hi = -1e30f, l_lo = 0.0f, l_hi = 0.0f;

    for (int kt = 0; kt < 32; kt++) {
        if (kt <= 29)      { CP_WAIT2(); }
        else if (kt == 30) { CP_WAIT1(); }
        else               { CP_WAIT0(); }
        __syncthreads();

        if (kt == 0) {
#pragma unroll
            for (int kc = 0; kc < 4; kc++)
                ldmatrix_x4(qf[kc], smem_u32(Qs + (w * 16 + l16) * TS + kc * 16 + lhi));
        }

        const int st = kt & 3;
        const __half* Kb = KV + st * ATTN_STAGE_ELE;
        const __half* Vb = Kb + ATTN_KV_ELE;

        float sfr[8][4];
#pragma unroll
        for (int ni = 0; ni < 8; ni++)
#pragma unroll
            for (int q = 0; q < 4; q++) sfr[ni][q] = 0.0f;
#pragma unroll
        for (int kc = 0; kc < 4; kc++) {
#pragma unroll
            for (int p = 0; p < 4; p++) {
                uint32_t t4[4];
                uint32_t addr = smem_u32(Kb + (p * 16 + ((lane >> 4) << 3) + (lane & 7)) * TS
                                         + kc * 16 + (((lane >> 3) & 1) << 3));
                ldmatrix_x4(t4, addr);
                mma_f16_f32(sfr[2 * p],     qf[kc], &t4[0]);
                mma_f16_f32(sfr[2 * p + 1], qf[kc], &t4[2]);
            }
        }

        float tl = -1e30f, th = -1e30f;
#pragma unroll
        for (int ni = 0; ni < 8; ni++) {
            tl = fmaxf(tl, fmaxf(sfr[ni][0], sfr[ni][1]));
            th = fmaxf(th, fmaxf(sfr[ni][2], sfr[ni][3]));
        }
        tl = fmaxf(tl, __shfl_xor_sync(0xffffffffu, tl, 1));
        tl = fmaxf(tl, __shfl_xor_sync(0xffffffffu, tl, 2));
        th = fmaxf(th, __shfl_xor_sync(0xffffffffu, th, 1));
        th = fmaxf(th, __shfl_xor_sync(0xffffffffu, th, 2));

        float mnl = fmaxf(m_lo, tl), mnh = fmaxf(m_hi, th);
        float al = __expf(m_lo - mnl), ah = __expf(m_hi - mnh);
        m_lo = mnl; m_hi = mnh;

        float sl = 0.0f, shi = 0.0f;
#pragma unroll
        for (int ni = 0; ni < 8; ni++) {
            sfr[ni][0] = __expf(sfr[ni][0] - m_lo);
            sfr[ni][1] = __expf(sfr[ni][1] - m_lo);
            sfr[ni][2] = __expf(sfr[ni][2] - m_hi);
            sfr[ni][3] = __expf(sfr[ni][3] - m_hi);
            sl  += sfr[ni][0] + sfr[ni][1];
            shi += sfr[ni][2] + sfr[ni][3];
        }
        l_lo = l_lo * al + sl;
        l_hi = l_hi * ah + shi;
#pragma unroll
        for (int ni = 0; ni < 8; ni++) {
            o[ni][0] *= al; o[ni][1] *= al;
            o[ni][2] *= ah; o[ni][3] *= ah;
        }

        uint32_t pu[4][4];
#pragma unroll
        for (int j = 0; j < 4; j++) {
            pu[j][0] = pack_f16(sfr[2 * j][0],     sfr[2 * j][1]);
            pu[j][1] = pack_f16(sfr[2 * j][2],     sfr[2 * j][3]);
            pu[j][2] = pack_f16(sfr[2 * j + 1][0], sfr[2 * j + 1][1]);
            pu[j][3] = pack_f16(sfr[2 * j + 1][2], sfr[2 * j + 1][3]);
        }

#pragma unroll
        for (int kc = 0; kc < 4; kc++) {
#pragma unroll
            for (int p = 0; p < 4; p++) {
                uint32_t t4[4];
                ldmatrix_x4t(t4, smem_u32(Vb + (kc * 16 + l16) * TS + p * 16 + lhi));
                mma_f16_f32(o[2 * p],     pu[kc], &t4[0]);
                mma_f16_f32(o[2 * p + 1], pu[kc], &t4[2]);
            }
        }

        if (kt + 3 < 32) { load_kv(kt + 3, (kt + 3) & 3); CP_COMMIT(); }
    }

    l_lo += __shfl_xor_sync(0xffffffffu, l_lo, 1);
    l_lo += __shfl_xor_sync(0xffffffffu, l_lo, 2);
    l_hi += __shfl_xor_sync(0xffffffffu, l_hi, 1);
    l_hi += __shfl_xor_sync(0xffffffffu, l_hi, 2);
    const float il = 1.0f / l_lo, ih = 1.0f / l_hi;

    const int row0 = b * SS + qt * 128 + w * 16 + g;
#pragma unroll
    for (int ni = 0; ni < 8; ni++) {
        const int col = h * HDIM + ni * 8 + 2 * tig;
        *(uint32_t*)(ctx + (size_t)row0 * HH + col) =
            pack_f16(o[ni][0] * il, o[ni][1] * il);
        *(uint32_t*)(ctx + (size_t)(row0 + 8) * HH + col) =
            pack_f16(o[ni][2] * ih, o[ni][3] * ih);
    }
}

// ============================================================================
// LayerNorm: one warp per row (R10-proven)
// ============================================================================
__global__ __launch_bounds__(256)
void layernorm_warp_kernel(const float* __restrict__ x, const float* __restrict__ gamma,
                           const float* __restrict__ beta, float* __restrict__ out)
{
    const int w = threadIdx.x >> 5;
    const int lane = threadIdx.x & 31;
    const int row = blockIdx.x * 8 + w;

    const float4* xp = (const float4*)(x + (size_t)row * HH);
    float4 v[8];
    float s = 0.0f, s2 = 0.0f;
#pragma unroll
    for (int i = 0; i < 8; i++) {
        v[i] = xp[lane + i * 32];
        s  += v[i].x + v[i].y + v[i].z + v[i].w;
        s2 += v[i].x * v[i].x + v[i].y * v[i].y + v[i].z * v[i].z + v[i].w * v[i].w;
    }
#pragma unroll
    for (int o = 16; o > 0; o >>= 1) {
        s  += __shfl_xor_sync(~0u, s, o);
        s2 += __shfl_xor_sync(~0u, s2, o);
    }
    const float mu = s * (1.0f / HH);
    const float var = s2 * (1.0f / HH) - mu * mu;
    const float rstd = rsqrtf(var + 1e-5f);

    const float4* gp = (const float4*)gamma;
    const float4* bp = (const float4*)beta;
    float4* op = (float4*)(out + (size_t)row * HH);
#pragma unroll
    for (int i = 0; i < 8; i++) {
        const float4 gm = gp[lane + i * 32];
        const float4 bt = bp[lane + i * 32];
        float4 o;
        o.x = (v[i].x - mu) * rstd * gm.x + bt.x;
        o.y = (v[i].y - mu) * rstd * gm.y + bt.y;
        o.z = (v[i].z - mu) * rstd * gm.z + bt.z;
        o.w = (v[i].w - mu) * rstd * gm.w + bt.w;
        op[lane + i * 32] = o;
    }
}

// ============================================================================
extern "C" void kernel_launch(void* const* d_in, const int* in_sizes, int n_in,
                              void* d_out, int out_size)
{
    const float* hidden  = (const float*)d_in[0];
    const float* w_qkv   = (const float*)d_in[1];
    const float* b_qkv   = (const float*)d_in[2];
    const float* w_dense = (const float*)d_in[3];
    const float* b_dense = (const float*)d_in[4];
    const float* gamma   = (const float*)d_in[5];
    const float* beta    = (const float*)d_in[6];
    float* out = (float*)d_out;

    __half *hid, *wq, *wd, *qkv, *ctx;
    float* x;
    cudaGetSymbolAddress((void**)&hid, g_hid_h);
    cudaGetSymbolAddress((void**)&wq,  g_wq_h);
    cudaGetSymbolAddress((void**)&wd,  g_wd_h);
    cudaGetSymbolAddress((void**)&qkv, g_qkv_h);
    cudaGetSymbolAddress((void**)&ctx, g_ctx_h);
    cudaGetSymbolAddress((void**)&x,   g_x);

    // 0) all fp32 -> fp16 conversions in one launch
    f2h_all_kernel<<<8192, 256>>>(hidden, w_qkv, w_dense, hid, wq, wd);

    // 1) QKV projection (fp16 MMA, fp32 accum) -> fp16, Q pre-scaled 1/8
    cudaFuncSetAttribute(gemm_f16_kernel<true>,
                         cudaFuncAttributeMaxDynamicSharedMemorySize, GEMM_SMEM_BYTES);
    gemm_f16_kernel<true><<<dim3(NQKV / 256, MTOT / 128), 256, GEMM_SMEM_BYTES>>>(
        hid, wq, b_qkv, nullptr, qkv, HH, NQKV);

    // 2) Flash attention (fp16 MMA, fp32 accum)
    cudaFuncSetAttribute(attn_f16_kernel,
                         cudaFuncAttributeMaxDynamicSharedMemorySize, ATTN_SMEM_BYTES);
    attn_f16_kernel<<<dim3(32, 16), 256, ATTN_SMEM_BYTES>>>(qkv, ctx);

    // 3) Dense projection (fp16 MMA, fp32 accum) + bias + residual -> fp32
    cudaFuncSetAttribute(gemm_f16_kernel<false>,
                         cudaFuncAttributeMaxDynamicSharedMemorySize, GEMM_SMEM_BYTES);
    gemm_f16_kernel<false><<<dim3(HH / 256, MTOT / 128), 256, GEMM_SMEM_BYTES>>>(
        ctx, wd, b_dense, hidden, x, HH, HH);

    // 4) LayerNorm (one warp per row)
    layernorm_warp_kernel<<<MTOT / 8, 256>>>(x, gamma, beta, out);
}